// round 1
// baseline (speedup 1.0000x reference)
#include <cuda_runtime.h>
#include <math.h>

#define FULLMASK 0xffffffffu
#define LOG2E 1.4426950408889634f

static constexpr int Bn  = 4;
static constexpr int T   = 512;
static constexpr int TPn = 1024;
static constexpr int Cn  = 32;
static constexpr int Kn  = 128;

// Scratch (device globals; no allocation allowed)
__device__ float2 g_ASD[Cn * Cn];            // (softplus(alpha), (softplus(delta)+EPS)*log2e)
__device__ float  g_SM[Cn];                  // softplus(mu)
__device__ float  g_p[Kn];                   // fine probs
__device__ int    g_segstart[Bn * (Cn + 1)]; // per-batch type segment offsets
__device__ float  g_segtime[Bn * T];         // type-sorted (stable in time) past times
__device__ float  g_segpref[Bn * T * Cn];    // inclusive prefix of exp2(SD2*pt) per (segment pos, c)

__device__ __forceinline__ float ex2f(float x) {
    float r; asm("ex2.approx.f32 %0, %1;" : "=f"(r) : "f"(x)); return r;
}
__device__ __forceinline__ float sp(float x) {   // stable softplus, matches jax.nn.softplus in fp32
    return fmaxf(x, 0.f) + log1pf(expf(-fabsf(x)));
}

__global__ __launch_bounds__(1024) void GHP_setup_kernel(
    const int* __restrict__ pe_g, const float* __restrict__ pt_g,
    const float* __restrict__ mu, const float* __restrict__ alpha,
    const float* __restrict__ delta, const float* __restrict__ cfl,
    const int* __restrict__ ftc)
{
    __shared__ float2 s_ASD[Cn * Cn];
    __shared__ int    s_pe[T];
    __shared__ float  s_pt[T];
    __shared__ int    s_typepos[T];
    __shared__ int    s_sorted[T];
    __shared__ int    s_cnt[Cn];
    __shared__ int    s_seg[Cn + 1];
    __shared__ float  s_den[Cn];
    __shared__ float  s_mx;

    const int tid  = threadIdx.x;
    const int b    = blockIdx.x;
    const int lane = tid & 31;
    const int warp = tid >> 5;

    // softplus tables (every block builds its smem copy; block 0 persists to gmem)
    {
        float sa  = sp(alpha[tid]);
        float sd2 = (sp(delta[tid]) + 2.2204460492503131e-16f) * LOG2E;
        float2 v  = make_float2(sa, sd2);
        s_ASD[tid] = v;
        if (b == 0) g_ASD[tid] = v;
    }
    if (tid < T) { s_pe[tid] = pe_g[b * T + tid]; s_pt[tid] = pt_g[b * T + tid]; }
    if (b == 0 && tid < Cn) g_SM[tid] = sp(mu[tid]);
    if (tid < Cn) s_den[tid] = 0.f;
    if (b == 0 && tid == 0) {
        float m = -1e30f;
        for (int k = 0; k < Kn; k++) m = fmaxf(m, cfl[k]);
        s_mx = m;
    }
    __syncthreads();

    // fine probs (block 0 only)
    if (b == 0 && tid < Kn) {
        float ek = expf(cfl[tid] - s_mx);
        atomicAdd(&s_den[ftc[tid]], ek);
    }
    __syncthreads();
    if (b == 0 && tid < Kn) {
        float ek = expf(cfl[tid] - s_mx);
        g_p[tid] = ek / s_den[ftc[tid]];
    }

    // ---- stable counting sort of events by type (warp 0) ----
    if (warp == 0) {
        s_cnt[lane] = 0;
        __syncwarp();
        for (int ch = 0; ch < T / 32; ch++) {
            int j = ch * 32 + lane;
            int e = s_pe[j];
            unsigned m = __match_any_sync(FULLMASK, e);
            int ldr = __ffs(m) - 1;
            int rk  = __popc(m & ((1u << lane) - 1u));
            int base = 0;
            if (lane == ldr) { base = s_cnt[e]; s_cnt[e] = base + __popc(m); }
            base = __shfl_sync(FULLMASK, base, ldr);
            s_typepos[j] = base + rk;
            __syncwarp();
        }
        // exclusive scan of counts -> segment starts
        int v = s_cnt[lane];
        int inc = v;
        #pragma unroll
        for (int o = 1; o < 32; o <<= 1) {
            int u = __shfl_up_sync(FULLMASK, inc, o);
            if (lane >= o) inc += u;
        }
        s_seg[lane] = inc - v;
        if (lane == 31) s_seg[32] = inc;   // == T
    }
    __syncthreads();

    if (tid < T) {
        int pos = s_seg[s_pe[tid]] + s_typepos[tid];
        s_sorted[pos] = tid;
    }
    if (tid < Cn + 1) g_segstart[b * (Cn + 1) + tid] = s_seg[tid];
    __syncthreads();

    // ---- per-(e,c) inclusive prefix of exp2(SD2*pt) over each type segment ----
    {
        int e    = warp;                       // warp <-> type
        int off  = s_seg[e];
        int cnt2 = s_seg[e + 1] - off;
        float sd2 = s_ASD[e * Cn + lane].y;
        float s = 0.f;
        for (int k2 = 0; k2 < cnt2; k2++) {
            int   j   = s_sorted[off + k2];
            float ptj = s_pt[j];
            s += ex2f(sd2 * ptj);
            g_segpref[((b * T) + off + k2) * Cn + lane] = s;
            if (lane == 0) g_segtime[b * T + off + k2] = ptj;
        }
    }
}

__global__ __launch_bounds__(256) void GHP_query_kernel(
    const float* __restrict__ tt, const int* __restrict__ ftc,
    float* __restrict__ out)
{
    __shared__ float2 s_ASD[Cn * Cn];
    __shared__ float  s_time[T];
    __shared__ int    s_seg[Cn + 1];
    __shared__ float  s_SM[Cn];
    __shared__ float  s_p[Kn];
    __shared__ int    s_ftc[Kn];

    const int tid = threadIdx.x;
    const int b   = blockIdx.x >> 7;   // 128 blocks (1024 queries / 8 per block) per batch

    for (int i = tid; i < Cn * Cn; i += 256) s_ASD[i] = g_ASD[i];
    for (int i = tid; i < T;       i += 256) s_time[i] = g_segtime[b * T + i];
    if (tid < Cn + 1) s_seg[tid] = g_segstart[b * (Cn + 1) + tid];
    if (tid < Cn)     s_SM[tid]  = g_SM[tid];
    if (tid < Kn)   { s_p[tid]   = g_p[tid]; s_ftc[tid] = ftc[tid]; }
    __syncthreads();

    const int warp = tid >> 5, lane = tid & 31;
    const int q = blockIdx.x * 8 + warp;       // q = b*TP + tp, in order
    const float t  = tt[q];
    const float tn = -t;

    float acc = 0.f;
    for (int e = 0; e < Cn; e++) {
        int off = s_seg[e];
        int m   = s_seg[e + 1] - off;
        // causal rank: # events of type e with pt < t (segment times nondecreasing)
        int n = 0;
        for (int s0 = 0; s0 < m; s0 += 32) {
            float v = (s0 + lane < m) ? s_time[off + s0 + lane] : 3.402823466e38f;
            unsigned bl = __ballot_sync(FULLMASK, v < t);
            int c1 = __popc(bl);
            n += c1;
            if (c1 < 32) break;
        }
        if (n > 0) {
            float2 asd = s_ASD[(e << 5) + lane];
            float  w    = ex2f(asd.y * tn);
            float  pref = g_segpref[((b * T) + off + n - 1) * Cn + lane];
            acc = fmaf(asd.x * w, pref, acc);
        }
    }
    acc += s_SM[lane];

    const size_t ob = (size_t)q * Kn;
    #pragma unroll
    for (int jj = 0; jj < 4; jj++) {
        int k = jj * 32 + lane;
        int f = s_ftc[k];
        float v = __shfl_sync(FULLMASK, acc, f);
        out[ob + k] = v * s_p[k];
    }
}

extern "C" void kernel_launch(void* const* d_in, const int* in_sizes, int n_in,
                              void* d_out, int out_size)
{
    const int*   pe    = (const int*)  d_in[0];  // past_event [B,T] int32
    const float* pt    = (const float*)d_in[1];  // past_time  [B,T]
    const float* tt    = (const float*)d_in[2];  // time_tensor [B,TP]
    const float* mu    = (const float*)d_in[3];  // [C]
    const float* alpha = (const float*)d_in[4];  // [C,C]
    const float* delta = (const float*)d_in[5];  // [C,C]
    const float* cfl   = (const float*)d_in[6];  // [K]
    const int*   ftc   = (const int*)  d_in[7];  // [K]
    float* out = (float*)d_out;                  // [B,TP,K] float32

    GHP_setup_kernel<<<Bn, 1024>>>(pe, pt, mu, alpha, delta, cfl, ftc);
    GHP_query_kernel<<<(Bn * TPn) / 8, 256>>>(tt, ftc, out);
}

// round 5
// speedup vs baseline: 2.2047x; 2.2047x over previous
#include <cuda_runtime.h>
#include <math.h>

#define FULLMASK 0xffffffffu
#define LOG2E 1.4426950408889634f

static constexpr int Bn  = 4;
static constexpr int T   = 512;
static constexpr int TPn = 1024;
static constexpr int Cn  = 32;
static constexpr int Kn  = 128;

// Scratch (device globals; no allocation allowed)
__device__ float2 g_ASD[Cn * Cn];            // (softplus(alpha), (softplus(delta)+EPS)*log2e)
__device__ float  g_SM[Cn];                  // softplus(mu)
__device__ float  g_p[Kn];                   // fine probs
__device__ int    g_segstart[Bn * (Cn + 1)]; // per-batch type segment offsets
__device__ float  g_segtime[Bn * T];         // type-sorted (stable in time) past times
__device__ float  g_segpref[Bn * T * Cn];    // inclusive prefix of exp2(SD2*pt) per (segment pos, c)

__device__ __forceinline__ float ex2f(float x) {
    float r; asm("ex2.approx.f32 %0, %1;" : "=f"(r) : "f"(x)); return r;
}
__device__ __forceinline__ float sp(float x) {   // stable softplus, matches jax.nn.softplus in fp32
    return fmaxf(x, 0.f) + log1pf(expf(-fabsf(x)));
}

__global__ __launch_bounds__(1024) void GHP_setup_kernel(
    const int* __restrict__ pe_g, const float* __restrict__ pt_g,
    const float* __restrict__ mu, const float* __restrict__ alpha,
    const float* __restrict__ delta, const float* __restrict__ cfl,
    const int* __restrict__ ftc)
{
    __shared__ float2 s_ASD[Cn * Cn];
    __shared__ int    s_pe[T];
    __shared__ float  s_pt[T];
    __shared__ int    s_typepos[T];
    __shared__ int    s_sorted[T];
    __shared__ int    s_cnt[Cn];
    __shared__ int    s_seg[Cn + 1];
    __shared__ float  s_den[Cn];
    __shared__ float  s_mx;

    const int tid  = threadIdx.x;
    const int b    = blockIdx.x;
    const int lane = tid & 31;
    const int warp = tid >> 5;

    // softplus tables (every block builds its smem copy; block 0 persists to gmem)
    {
        float sa  = sp(alpha[tid]);
        float sd2 = (sp(delta[tid]) + 2.2204460492503131e-16f) * LOG2E;
        float2 v  = make_float2(sa, sd2);
        s_ASD[tid] = v;
        if (b == 0) g_ASD[tid] = v;
    }
    if (tid < T) { s_pe[tid] = pe_g[b * T + tid]; s_pt[tid] = pt_g[b * T + tid]; }
    if (b == 0 && tid < Cn) g_SM[tid] = sp(mu[tid]);
    if (tid < Cn) s_den[tid] = 0.f;

    // parallel max of cf_logits (block 0, warp 0): 4 loads + shfl tree
    if (b == 0 && warp == 0) {
        float v = fmaxf(fmaxf(cfl[lane], cfl[lane + 32]),
                        fmaxf(cfl[lane + 64], cfl[lane + 96]));
        #pragma unroll
        for (int o = 16; o > 0; o >>= 1)
            v = fmaxf(v, __shfl_xor_sync(FULLMASK, v, o));
        if (lane == 0) s_mx = v;
    }
    __syncthreads();

    // fine probs (block 0 only)
    if (b == 0 && tid < Kn) {
        float ek = expf(cfl[tid] - s_mx);
        atomicAdd(&s_den[ftc[tid]], ek);
    }
    __syncthreads();
    if (b == 0 && tid < Kn) {
        float ek = expf(cfl[tid] - s_mx);
        g_p[tid] = ek / s_den[ftc[tid]];
    }

    // ---- stable counting sort of events by type (warp 0) ----
    if (warp == 0) {
        s_cnt[lane] = 0;
        __syncwarp();
        for (int ch = 0; ch < T / 32; ch++) {
            int j = ch * 32 + lane;
            int e = s_pe[j];
            unsigned m = __match_any_sync(FULLMASK, e);
            int ldr = __ffs(m) - 1;
            int rk  = __popc(m & ((1u << lane) - 1u));
            int base = 0;
            if (lane == ldr) { base = s_cnt[e]; s_cnt[e] = base + __popc(m); }
            base = __shfl_sync(FULLMASK, base, ldr);
            s_typepos[j] = base + rk;
            __syncwarp();
        }
        // exclusive scan of counts -> segment starts
        int v = s_cnt[lane];
        int inc = v;
        #pragma unroll
        for (int o = 1; o < 32; o <<= 1) {
            int u = __shfl_up_sync(FULLMASK, inc, o);
            if (lane >= o) inc += u;
        }
        s_seg[lane] = inc - v;
        if (lane == 31) s_seg[32] = inc;   // == T
    }
    __syncthreads();

    if (tid < T) {
        int pos = s_seg[s_pe[tid]] + s_typepos[tid];
        s_sorted[pos] = tid;
        g_segtime[b * T + pos] = s_pt[tid];   // parallel coalesced-ish scatter
    }
    if (tid < Cn + 1) g_segstart[b * (Cn + 1) + tid] = s_seg[tid];
    __syncthreads();

    // ---- per-(e,c) inclusive prefix of exp2(SD2*pt) over each type segment ----
    {
        int e    = warp;                       // warp <-> type
        int off  = s_seg[e];
        int cnt2 = s_seg[e + 1] - off;
        float sd2 = s_ASD[e * Cn + lane].y;
        float s = 0.f;
        for (int k2 = 0; k2 < cnt2; k2++) {
            int   j   = s_sorted[off + k2];
            float ptj = s_pt[j];
            s += ex2f(sd2 * ptj);
            g_segpref[((b * T) + off + k2) * Cn + lane] = s;
        }
    }
}

__global__ __launch_bounds__(256) void GHP_query_kernel(
    const float* __restrict__ tt, const int* __restrict__ ftc,
    float* __restrict__ out)
{
    __shared__ float2 s_ASD[Cn * Cn];
    __shared__ float  s_time[T];
    __shared__ int    s_seg[Cn + 1];
    __shared__ float  s_SM[Cn];
    __shared__ float  s_p[Kn];
    __shared__ int    s_ftc[Kn];

    const int tid = threadIdx.x;
    const int b   = blockIdx.x >> 7;   // 128 blocks (1024 queries / 8 warps per block) per batch

    for (int i = tid; i < Cn * Cn; i += 256) s_ASD[i] = g_ASD[i];
    for (int i = tid; i < T;       i += 256) s_time[i] = g_segtime[b * T + i];
    if (tid < Cn + 1) s_seg[tid] = g_segstart[b * (Cn + 1) + tid];
    if (tid < Cn)     s_SM[tid]  = g_SM[tid];
    if (tid < Kn)   { s_p[tid]   = g_p[tid]; s_ftc[tid] = ftc[tid]; }
    __syncthreads();

    const int warp = tid >> 5, lane = tid & 31;
    const int q = blockIdx.x * 8 + warp;       // q = b*TP + tp, in order
    const float t  = tt[q];
    const float tn = -t;

    // ---- phase 1: lane e binary-searches its own (sorted) type segment ----
    // idx_l = global (within-batch) position of the last causal event of type 'lane', or -1
    int off_l = s_seg[lane];
    int m_l   = s_seg[lane + 1] - off_l;
    int lo = 0, hi = m_l;
    while (lo < hi) {
        int mid = (lo + hi) >> 1;
        if (s_time[off_l + mid] < t) lo = mid + 1; else hi = mid;
    }
    const int idx_l = (lo > 0) ? (off_l + lo - 1) : -1;

    // ---- phase 2: 32 independent coalesced prefix-row loads, fma chain ----
    const float* __restrict__ pref_b = g_segpref + (size_t)b * T * Cn;
    float acc = 0.f;
    #pragma unroll
    for (int e = 0; e < Cn; e++) {
        int idx = __shfl_sync(FULLMASK, idx_l, e);
        float2 asd = s_ASD[(e << 5) + lane];
        float  w   = asd.x * ex2f(asd.y * tn);
        if (idx >= 0) {
            float pref = pref_b[(size_t)idx * Cn + lane];
            acc = fmaf(w, pref, acc);
        }
    }
    acc += s_SM[lane];

    const size_t ob = (size_t)q * Kn;
    #pragma unroll
    for (int jj = 0; jj < 4; jj++) {
        int k = jj * 32 + lane;
        int f = s_ftc[k];
        float v = __shfl_sync(FULLMASK, acc, f);
        out[ob + k] = v * s_p[k];
    }
}

extern "C" void kernel_launch(void* const* d_in, const int* in_sizes, int n_in,
                              void* d_out, int out_size)
{
    const int*   pe    = (const int*)  d_in[0];  // past_event [B,T] int32
    const float* pt    = (const float*)d_in[1];  // past_time  [B,T]
    const float* tt    = (const float*)d_in[2];  // time_tensor [B,TP]
    const float* mu    = (const float*)d_in[3];  // [C]
    const float* alpha = (const float*)d_in[4];  // [C,C]
    const float* delta = (const float*)d_in[5];  // [C,C]
    const float* cfl   = (const float*)d_in[6];  // [K]
    const int*   ftc   = (const int*)  d_in[7];  // [K]
    float* out = (float*)d_out;                  // [B,TP,K] float32

    GHP_setup_kernel<<<Bn, 1024>>>(pe, pt, mu, alpha, delta, cfl, ftc);
    GHP_query_kernel<<<(Bn * TPn) / 8, 256>>>(tt, ftc, out);
}

// round 6
// speedup vs baseline: 3.2575x; 1.4775x over previous
#include <cuda_runtime.h>
#include <math.h>

#define FULLMASK 0xffffffffu
#define LOG2E 1.4426950408889634f

static constexpr int Bn  = 4;
static constexpr int T   = 512;
static constexpr int TPn = 1024;
static constexpr int Cn  = 32;
static constexpr int Kn  = 128;

// ---- dynamic shared memory layout (bytes) ----
static constexpr int SM_PREF    = 0;                         // float[T*Cn]   = 65536
static constexpr int SM_ASD     = SM_PREF + T * Cn * 4;      // float2[Cn*Cn] = 8192
static constexpr int SM_TIME    = SM_ASD + Cn * Cn * 8;      // float[T]      = 2048
static constexpr int SM_PT      = SM_TIME + T * 4;           // float[T]      = 2048
static constexpr int SM_PE      = SM_PT + T * 4;             // int[T]        = 2048
static constexpr int SM_TYPEPOS = SM_PE + T * 4;             // int[T]        = 2048
static constexpr int SM_SEG     = SM_TYPEPOS + T * 4;        // int[Cn+1]
static constexpr int SM_CNT     = SM_SEG + (Cn + 1) * 4;     // int[Cn]
static constexpr int SM_SMU     = SM_CNT + Cn * 4;           // float[Cn]
static constexpr int SM_P       = SM_SMU + Cn * 4;           // float[Kn]
static constexpr int SM_FTC     = SM_P + Kn * 4;             // int[Kn]
static constexpr int SM_DEN     = SM_FTC + Kn * 4;           // float[Cn]
static constexpr int SM_TOTAL   = SM_DEN + Cn * 4;           // ~83.3 KB

__device__ __forceinline__ float ex2f(float x) {
    float r; asm("ex2.approx.f32 %0, %1;" : "=f"(r) : "f"(x)); return r;
}
__device__ __forceinline__ float sp(float x) {   // stable softplus, matches jax.nn.softplus fp32
    return fmaxf(x, 0.f) + log1pf(expf(-fabsf(x)));
}

__global__ __launch_bounds__(1024) void GHP_fused_kernel(
    const int* __restrict__ pe_g, const float* __restrict__ pt_g,
    const float* __restrict__ tt, const float* __restrict__ mu,
    const float* __restrict__ alpha, const float* __restrict__ delta,
    const float* __restrict__ cfl, const int* __restrict__ ftc,
    float* __restrict__ out)
{
    extern __shared__ char smem[];
    float*  s_pref    = (float*) (smem + SM_PREF);
    float2* s_ASD     = (float2*)(smem + SM_ASD);
    float*  s_time    = (float*) (smem + SM_TIME);
    float*  s_pt      = (float*) (smem + SM_PT);
    int*    s_pe      = (int*)   (smem + SM_PE);
    int*    s_typepos = (int*)   (smem + SM_TYPEPOS);
    int*    s_seg     = (int*)   (smem + SM_SEG);
    int*    s_cnt     = (int*)   (smem + SM_CNT);
    float*  s_SM      = (float*) (smem + SM_SMU);
    float*  s_p       = (float*) (smem + SM_P);
    int*    s_ftc     = (int*)   (smem + SM_FTC);
    float*  s_den     = (float*) (smem + SM_DEN);

    const int tid  = threadIdx.x;
    const int lane = tid & 31;
    const int warp = tid >> 5;
    const int b    = blockIdx.x >> 5;   // 32 blocks per batch
    const int qb   = blockIdx.x & 31;   // query group within batch

    // ---- phase A: parallel loads + softplus tables ----
    {
        float sa  = sp(alpha[tid]);
        float sd2 = (sp(delta[tid]) + 2.2204460492503131e-16f) * LOG2E;
        s_ASD[tid] = make_float2(sa, sd2);
    }
    if (tid < T) { s_pe[tid] = pe_g[b * T + tid]; s_pt[tid] = pt_g[b * T + tid]; }
    if (tid < Cn) { s_SM[tid] = sp(mu[tid]); s_den[tid] = 0.f; }
    __syncthreads();

    // ---- phase B (parallel warps): warp 0 sorts, warp 1 does fine-probs ----
    if (warp == 0) {
        // stable counting sort of events by type
        s_cnt[lane] = 0;
        __syncwarp();
        for (int ch = 0; ch < T / 32; ch++) {
            int j = ch * 32 + lane;
            int e = s_pe[j];
            unsigned m = __match_any_sync(FULLMASK, e);
            int ldr = __ffs(m) - 1;
            int rk  = __popc(m & ((1u << lane) - 1u));
            int base = 0;
            if (lane == ldr) { base = s_cnt[e]; s_cnt[e] = base + __popc(m); }
            base = __shfl_sync(FULLMASK, base, ldr);
            s_typepos[j] = base + rk;
            __syncwarp();
        }
        int v = s_cnt[lane];
        int inc = v;
        #pragma unroll
        for (int o = 1; o < 32; o <<= 1) {
            int u = __shfl_up_sync(FULLMASK, inc, o);
            if (lane >= o) inc += u;
        }
        s_seg[lane] = inc - v;
        if (lane == 31) s_seg[32] = inc;   // == T
    } else if (warp == 1) {
        // fine probs, entirely within one warp
        float c0 = cfl[lane], c1 = cfl[lane + 32], c2 = cfl[lane + 64], c3 = cfl[lane + 96];
        float mx = fmaxf(fmaxf(c0, c1), fmaxf(c2, c3));
        #pragma unroll
        for (int o = 16; o > 0; o >>= 1)
            mx = fmaxf(mx, __shfl_xor_sync(FULLMASK, mx, o));
        float ek[4] = { expf(c0 - mx), expf(c1 - mx), expf(c2 - mx), expf(c3 - mx) };
        int   fk[4];
        #pragma unroll
        for (int j = 0; j < 4; j++) {
            int k = j * 32 + lane;
            fk[j] = ftc[k];
            s_ftc[k] = fk[j];
            atomicAdd(&s_den[fk[j]], ek[j]);
        }
        __syncwarp();
        #pragma unroll
        for (int j = 0; j < 4; j++) {
            int k = j * 32 + lane;
            s_p[k] = ek[j] / s_den[fk[j]];
        }
    }
    __syncthreads();

    // ---- phase C: scatter times into type-sorted order ----
    if (tid < T) {
        int pos = s_seg[s_pe[tid]] + s_typepos[tid];
        s_time[pos] = s_pt[tid];
    }
    __syncthreads();

    // ---- phase D: per-(e,c) inclusive prefix of exp2(sd2*pt) ----
    {
        int   e    = warp;                      // warp <-> type
        int   off  = s_seg[e];
        int   cnt2 = s_seg[e + 1] - off;
        float sd2  = s_ASD[e * Cn + lane].y;
        float s = 0.f;
        for (int k2 = 0; k2 < cnt2; k2++) {
            s += ex2f(sd2 * s_time[off + k2]);
            s_pref[(off + k2) * Cn + lane] = s;
        }
    }
    __syncthreads();

    // ---- phase E: one query per warp ----
    const int   q  = (b * TPn) + qb * 32 + warp;
    const float t  = tt[q];
    const float tn = -t;

    // lane e binary-searches its own type segment: last causal index (within batch order), or -1
    int off_l = s_seg[lane];
    int m_l   = s_seg[lane + 1] - off_l;
    int lo = 0, hi = m_l;
    while (lo < hi) {
        int mid = (lo + hi) >> 1;
        if (s_time[off_l + mid] < t) lo = mid + 1; else hi = mid;
    }
    const int idx_l = (lo > 0) ? (off_l + lo - 1) : -1;

    float acc = 0.f;
    #pragma unroll
    for (int e = 0; e < Cn; e++) {
        int    idx = __shfl_sync(FULLMASK, idx_l, e);
        float2 asd = s_ASD[(e << 5) + lane];
        float  w   = asd.x * ex2f(asd.y * tn);
        if (idx >= 0)
            acc = fmaf(w, s_pref[idx * Cn + lane], acc);
    }
    acc += s_SM[lane];

    const size_t ob = (size_t)q * Kn;
    #pragma unroll
    for (int jj = 0; jj < 4; jj++) {
        int k = jj * 32 + lane;
        int f = s_ftc[k];
        float v = __shfl_sync(FULLMASK, acc, f);
        out[ob + k] = v * s_p[k];
    }
}

extern "C" void kernel_launch(void* const* d_in, const int* in_sizes, int n_in,
                              void* d_out, int out_size)
{
    const int*   pe    = (const int*)  d_in[0];  // past_event [B,T] int32
    const float* pt    = (const float*)d_in[1];  // past_time  [B,T]
    const float* tt    = (const float*)d_in[2];  // time_tensor [B,TP]
    const float* mu    = (const float*)d_in[3];  // [C]
    const float* alpha = (const float*)d_in[4];  // [C,C]
    const float* delta = (const float*)d_in[5];  // [C,C]
    const float* cfl   = (const float*)d_in[6];  // [K]
    const int*   ftc   = (const int*)  d_in[7];  // [K]
    float* out = (float*)d_out;                  // [B,TP,K] float32

    cudaFuncSetAttribute(GHP_fused_kernel,
                         cudaFuncAttributeMaxDynamicSharedMemorySize, SM_TOTAL);
    GHP_fused_kernel<<<Bn * 32, 1024, SM_TOTAL>>>(pe, pt, tt, mu, alpha, delta,
                                                  cfl, ftc, out);
}